// round 2
// baseline (speedup 1.0000x reference)
#include <cuda_runtime.h>

// x: [32, 256, 64, 64] f32; weight: [256, 256, 3, 3] f32; bias: [256] f32
// out: [32, 256, 1, 1] f32   (spatial = 128*128 = 16384)
#define B_   32
#define C_   256
#define O_   256
#define HW_  4096            // 64*64
#define BC_  (B_ * C_)       // 8192
#define CO_  (C_ * O_)       // 65536
#define WPREP_BLOCKS (CO_ / 256)   // 256

// Scratch (no allocations allowed)
__device__ float4 g_statsT[BC_];  // TRANSPOSED: [c][b] -> (T, R0, C0, x00)
__device__ float4 g_wcat[CO_];    // [c][o] -> (Wsum, -Wkh0, -Wkw0, W00)

// ---------------------------------------------------------------------------
// Kernel A: fused stats (blocks 0..8191) + weight folding (blocks 8192..8447).
// Stats: one block per (b,c) 16 KB image, 256 threads, 4x float4 per thread.
// ---------------------------------------------------------------------------
__global__ void __launch_bounds__(256) fused_prep_kernel(const float* __restrict__ x,
                                                         const float* __restrict__ w) {
    if (blockIdx.x < BC_) {
        // ---------------- stats part ----------------
        const int bc = blockIdx.x;
        const float4* __restrict__ p4 =
            reinterpret_cast<const float4*>(x + (size_t)bc * HW_);
        const int t = threadIdx.x;

        float s = 0.f, r0 = 0.f, c0 = 0.f, v00 = 0.f;

        #pragma unroll
        for (int i = 0; i < 4; i++) {
            const int j = t + i * 256;        // float4 index 0..1023
            float4 v = p4[j];
            float vs = v.x + v.y + v.z + v.w;
            s += vs;
            if (j < 16)          r0 += vs;    // row 0 = first 64 elems
            if ((j & 15) == 0)   c0 += v.x;   // col 0 = elem % 64 == 0
            if (j == 0)          v00 = v.x;
        }

        #pragma unroll
        for (int off = 16; off > 0; off >>= 1) {
            s  += __shfl_xor_sync(0xFFFFFFFFu, s,  off);
            r0 += __shfl_xor_sync(0xFFFFFFFFu, r0, off);
            c0 += __shfl_xor_sync(0xFFFFFFFFu, c0, off);
        }

        __shared__ float ss[8], sr[8], sc[8];
        __shared__ float sv00;
        const int warp = t >> 5, lane = t & 31;
        if (t == 0) sv00 = v00;
        if (lane == 0) { ss[warp] = s; sr[warp] = r0; sc[warp] = c0; }
        __syncthreads();

        if (warp == 0) {
            float fs = (lane < 8) ? ss[lane] : 0.f;
            float fr = (lane < 8) ? sr[lane] : 0.f;
            float fc = (lane < 8) ? sc[lane] : 0.f;
            #pragma unroll
            for (int off = 4; off > 0; off >>= 1) {
                fs += __shfl_xor_sync(0xFFFFFFFFu, fs, off);
                fr += __shfl_xor_sync(0xFFFFFFFFu, fr, off);
                fc += __shfl_xor_sync(0xFFFFFFFFu, fc, off);
            }
            if (lane == 0) {
                const int b = bc >> 8;        // bc / 256
                const int c = bc & 255;       // bc % 256
                g_statsT[c * B_ + b] = make_float4(fs, fr, fc, sv00);
            }
        }
    } else {
        // ---------------- weight folding part ----------------
        const int i = (blockIdx.x - BC_) * 256 + threadIdx.x;   // (c*256 + o)
        const float* p = w + (size_t)i * 9;
        float w00 = p[0], w01 = p[1], w02 = p[2];
        float w10 = p[3], w11 = p[4], w12 = p[5];
        float w20 = p[6], w21 = p[7], w22 = p[8];
        float wsum = ((w00 + w01) + (w02 + w10)) + ((w11 + w12) + (w20 + w21)) + w22;
        float wkh0 = w00 + w01 + w02;   // kh == 0 row
        float wkw0 = w00 + w10 + w20;   // kw == 0 col
        g_wcat[i] = make_float4(wsum, -wkh0, -wkw0, w00);
    }
}

// ---------------------------------------------------------------------------
// Kernel B: micro-GEMM  S[b,o] = sum_c dot4(statsT[c][b], wcat[c][o]).
// grid = 32 blocks (8 o's each), warp = one o, lane = b.
//   - wcat load is warp-uniform  -> 1 sector broadcast
//   - statsT load is coalesced   -> 512 B per warp, L1-resident across warps
// Two accumulators break the FMA dependency chain.
// ---------------------------------------------------------------------------
__global__ void __launch_bounds__(256) gemm_kernel(const float* __restrict__ bias,
                                                   float* __restrict__ out) {
    const int warp = threadIdx.x >> 5;
    const int b    = threadIdx.x & 31;           // lane = batch
    const int o    = blockIdx.x * 8 + warp;      // output channel

    float acc0 = 0.f, acc1 = 0.f;

    #pragma unroll 8
    for (int c = 0; c < C_; c += 2) {
        float4 a0 = g_statsT[c * B_ + b];
        float4 w0 = g_wcat[c * O_ + o];
        float4 a1 = g_statsT[(c + 1) * B_ + b];
        float4 w1 = g_wcat[(c + 1) * O_ + o];
        acc0 = fmaf(a0.x, w0.x, acc0);
        acc1 = fmaf(a1.x, w1.x, acc1);
        acc0 = fmaf(a0.y, w0.y, acc0);
        acc1 = fmaf(a1.y, w1.y, acc1);
        acc0 = fmaf(a0.z, w0.z, acc0);
        acc1 = fmaf(a1.z, w1.z, acc1);
        acc0 = fmaf(a0.w, w0.w, acc0);
        acc1 = fmaf(a1.w, w1.w, acc1);
    }

    float s = acc0 + acc1;
    out[b * O_ + o] = 2.0f * (s * (1.0f / 16384.0f) + bias[o]);
}

// ---------------------------------------------------------------------------
extern "C" void kernel_launch(void* const* d_in, const int* in_sizes, int n_in,
                              void* d_out, int out_size) {
    const float* x    = (const float*)d_in[0];
    const float* wgt  = (const float*)d_in[1];
    const float* bias = (const float*)d_in[2];
    float* out        = (float*)d_out;

    fused_prep_kernel<<<BC_ + WPREP_BLOCKS, 256>>>(x, wgt);
    gemm_kernel<<<O_ / 8, 256>>>(bias, out);
}

// round 3
// speedup vs baseline: 2.7677x; 2.7677x over previous
#include <cuda_runtime.h>

// x: [32, 256, 64, 64] f32; weight: [256, 256, 3, 3] f32; bias: [256] f32
// out: [32, 256, 1, 1] f32   (spatial = 128*128 = 16384)
#define B_   32
#define C_   256
#define O_   256
#define HW_  4096            // 64*64
#define BC_  (B_ * C_)       // 8192
#define CO_  (C_ * O_)       // 65536
#define WPREP_BLOCKS (CO_ / 256)   // 256

// Scratch (no allocations allowed)
__device__ float4 g_statsT[BC_];  // [c][b] -> (T, R0, C0, x00)
__device__ float4 g_wcatT[CO_];   // TRANSPOSED: [o][c] -> (Wsum, -Wkh0, -Wkw0, W00)

// ---------------------------------------------------------------------------
// Kernel A: fused stats (blocks 0..8191) + weight folding (blocks 8192..8447).
// Stats: one block per (b,c) 16 KB image, 256 threads, 4x float4 per thread.
// 134 MB streaming read, ~74% DRAM — this is the roofline kernel.
// ---------------------------------------------------------------------------
__global__ void __launch_bounds__(256) fused_prep_kernel(const float* __restrict__ x,
                                                         const float* __restrict__ w) {
    if (blockIdx.x < BC_) {
        // ---------------- stats part ----------------
        const int bc = blockIdx.x;
        const float4* __restrict__ p4 =
            reinterpret_cast<const float4*>(x + (size_t)bc * HW_);
        const int t = threadIdx.x;

        float s = 0.f, r0 = 0.f, c0 = 0.f, v00 = 0.f;

        #pragma unroll
        for (int i = 0; i < 4; i++) {
            const int j = t + i * 256;        // float4 index 0..1023
            float4 v = p4[j];
            float vs = v.x + v.y + v.z + v.w;
            s += vs;
            if (j < 16)          r0 += vs;    // row 0 = first 64 elems
            if ((j & 15) == 0)   c0 += v.x;   // col 0 = elem % 64 == 0
            if (j == 0)          v00 = v.x;
        }

        #pragma unroll
        for (int off = 16; off > 0; off >>= 1) {
            s  += __shfl_xor_sync(0xFFFFFFFFu, s,  off);
            r0 += __shfl_xor_sync(0xFFFFFFFFu, r0, off);
            c0 += __shfl_xor_sync(0xFFFFFFFFu, c0, off);
        }

        __shared__ float ss[8], sr[8], sc[8];
        __shared__ float sv00;
        const int warp = t >> 5, lane = t & 31;
        if (t == 0) sv00 = v00;
        if (lane == 0) { ss[warp] = s; sr[warp] = r0; sc[warp] = c0; }
        __syncthreads();

        if (warp == 0) {
            float fs = (lane < 8) ? ss[lane] : 0.f;
            float fr = (lane < 8) ? sr[lane] : 0.f;
            float fc = (lane < 8) ? sc[lane] : 0.f;
            #pragma unroll
            for (int off = 4; off > 0; off >>= 1) {
                fs += __shfl_xor_sync(0xFFFFFFFFu, fs, off);
                fr += __shfl_xor_sync(0xFFFFFFFFu, fr, off);
                fc += __shfl_xor_sync(0xFFFFFFFFu, fc, off);
            }
            if (lane == 0) {
                const int b = bc >> 8;        // bc / 256
                const int c = bc & 255;       // bc % 256
                g_statsT[c * B_ + b] = make_float4(fs, fr, fc, sv00);
            }
        }
    } else {
        // ---------------- weight folding part ----------------
        const int i = (blockIdx.x - BC_) * 256 + threadIdx.x;   // i = c*256 + o
        const int c = i >> 8;
        const int o = i & 255;
        const float* p = w + (size_t)i * 9;
        float w00 = p[0], w01 = p[1], w02 = p[2];
        float w10 = p[3], w11 = p[4], w12 = p[5];
        float w20 = p[6], w21 = p[7], w22 = p[8];
        float wsum = ((w00 + w01) + (w02 + w10)) + ((w11 + w12) + (w20 + w21)) + w22;
        float wkh0 = w00 + w01 + w02;   // kh == 0 row
        float wkw0 = w00 + w10 + w20;   // kw == 0 col
        g_wcatT[o * C_ + c] = make_float4(wsum, -wkh0, -wkw0, w00);
    }
}

// ---------------------------------------------------------------------------
// Kernel B: micro-GEMM  S[b,o] = sum_c dot4(statsT[c][b], wcatT[o][c]).
// grid = 256 blocks (one per output channel o), 256 threads.
//   stage 1: coalesced load of wcatT[o][*] (4 KB) into smem
//   stage 2: thread = (b = lane, cg = warp); 32 coalesced statsT loads
//            (512 B/warp) + smem broadcast; dual accumulators
//   stage 3: 8-way smem reduction, epilogue 2*(S/16384 + bias)
// ---------------------------------------------------------------------------
__global__ void __launch_bounds__(256) gemm_kernel(const float* __restrict__ bias,
                                                   float* __restrict__ out) {
    const int o = blockIdx.x;
    const int t = threadIdx.x;

    __shared__ float4 wsm[C_];
    __shared__ float  red[8][33];

    wsm[t] = g_wcatT[o * C_ + t];
    __syncthreads();

    const int b  = t & 31;   // lane = batch
    const int cg = t >> 5;   // warp = c-group of 32

    float acc0 = 0.f, acc1 = 0.f;
    const int cbase = cg * 32;

    #pragma unroll 8
    for (int k = 0; k < 32; k += 2) {
        const int c = cbase + k;
        float4 a0 = g_statsT[c * B_ + b];
        float4 w0 = wsm[c];
        float4 a1 = g_statsT[(c + 1) * B_ + b];
        float4 w1 = wsm[c + 1];
        acc0 = fmaf(a0.x, w0.x, acc0);
        acc1 = fmaf(a1.x, w1.x, acc1);
        acc0 = fmaf(a0.y, w0.y, acc0);
        acc1 = fmaf(a1.y, w1.y, acc1);
        acc0 = fmaf(a0.z, w0.z, acc0);
        acc1 = fmaf(a1.z, w1.z, acc1);
        acc0 = fmaf(a0.w, w0.w, acc0);
        acc1 = fmaf(a1.w, w1.w, acc1);
    }

    red[cg][b] = acc0 + acc1;
    __syncthreads();

    if (t < 32) {
        float s = 0.f;
        #pragma unroll
        for (int g = 0; g < 8; g++) s += red[g][t];
        out[t * O_ + o] = 2.0f * (s * (1.0f / 16384.0f) + bias[o]);
    }
}

// ---------------------------------------------------------------------------
extern "C" void kernel_launch(void* const* d_in, const int* in_sizes, int n_in,
                              void* d_out, int out_size) {
    const float* x    = (const float*)d_in[0];
    const float* wgt  = (const float*)d_in[1];
    const float* bias = (const float*)d_in[2];
    float* out        = (float*)d_out;

    fused_prep_kernel<<<BC_ + WPREP_BLOCKS, 256>>>(x, wgt);
    gemm_kernel<<<O_, 256>>>(bias, out);
}